// round 2
// baseline (speedup 1.0000x reference)
#include <cuda_runtime.h>
#include <math.h>
#include <float.h>

// SmartPool2d: per-(n,c) 128x128 image -> threshold bbox -> antialiased
// bilinear resize of the crop to 64x64, expressed as two sparse (<=6-tap)
// weighted reductions. One CTA per image; image staged in shared memory so
// HBM is read exactly once (256 MB in, 64 MB out).

#define HH 128
#define WW 128
#define OH 64
#define OW 64
#define KT 6
#define NTHREADS 512
#define NWARPS (NTHREADS / 32)

__global__ __launch_bounds__(NTHREADS, 2)
void smartpool2d_kernel(const float* __restrict__ x, float* __restrict__ out) {
    extern __shared__ float sm[];
    float* simg = sm;                 // 128*128 = 16384 floats (64 KB)
    float* stmp = sm + HH * WW;       // 64*128  =  8192 floats (32 KB)

    __shared__ float s_wh[OH][KT];
    __shared__ float s_ww[OW][KT];
    __shared__ int   s_jh[OH];
    __shared__ int   s_jw[OW];
    __shared__ float s_red[NWARPS * 4];
    __shared__ float s_thr;
    __shared__ float s_bbox[4];       // loH, hiH, loW, hiW

    const int tid  = threadIdx.x;
    const int warp = tid >> 5;
    const int lane = tid & 31;
    const int img  = blockIdx.x;
    const float* src = x + (size_t)img * (HH * WW);

    // ---- Pass 1: load image to smem (float4) + per-thread max ----
    float m = -FLT_MAX;
    {
        const float4* s4 = (const float4*)src;
        float4* d4 = (float4*)simg;
        #pragma unroll 4
        for (int i = tid; i < (HH * WW) / 4; i += NTHREADS) {
            float4 v = s4[i];
            d4[i] = v;
            m = fmaxf(m, fmaxf(fmaxf(v.x, v.y), fmaxf(v.z, v.w)));
        }
    }
    #pragma unroll
    for (int off = 16; off; off >>= 1)
        m = fmaxf(m, __shfl_xor_sync(0xffffffffu, m, off));
    if (lane == 0) s_red[warp] = m;
    __syncthreads();
    if (tid == 0) {
        float mm = s_red[0];
        #pragma unroll
        for (int i = 1; i < NWARPS; i++) mm = fmaxf(mm, s_red[i]);
        s_thr = 0.1f * mm;
    }
    __syncthreads();
    const float thr = s_thr;

    // ---- Pass 2: bbox (faithful replication of the reference quirk math) ----
    // value_rowmin(h,w) = (h==0 ? 1e5 : 0) + table*h   (table*0 == 0 at h==0)
    float xmin = 3e38f, xmax = -3e38f, ymin = 3e38f, ymax = -3e38f;
    for (int i = tid; i < HH * WW; i += NTHREADS) {
        int h = i >> 7, w = i & 127;
        float tab = (simg[i] >= thr) ? 1.0f : 0.0f;
        float vh = tab * (float)h;
        float vw = tab * (float)w;
        float a = (h == 0) ? 1e5f  : vh;
        float b = (h == 0) ? -1e5f : vh;
        float c = (w == 0) ? 1e5f  : vw;
        float d = (w == 0) ? -1e5f : vw;
        xmin = fminf(xmin, a); xmax = fmaxf(xmax, b);
        ymin = fminf(ymin, c); ymax = fmaxf(ymax, d);
    }
    #pragma unroll
    for (int off = 16; off; off >>= 1) {
        xmin = fminf(xmin, __shfl_xor_sync(0xffffffffu, xmin, off));
        xmax = fmaxf(xmax, __shfl_xor_sync(0xffffffffu, xmax, off));
        ymin = fminf(ymin, __shfl_xor_sync(0xffffffffu, ymin, off));
        ymax = fmaxf(ymax, __shfl_xor_sync(0xffffffffu, ymax, off));
    }
    if (lane == 0) {
        s_red[warp * 4 + 0] = xmin;
        s_red[warp * 4 + 1] = xmax;
        s_red[warp * 4 + 2] = ymin;
        s_red[warp * 4 + 3] = ymax;
    }
    __syncthreads();
    if (tid == 0) {
        float a = s_red[0], b = s_red[1], c = s_red[2], d = s_red[3];
        #pragma unroll
        for (int i = 1; i < NWARPS; i++) {
            a = fminf(a, s_red[i * 4 + 0]);
            b = fmaxf(b, s_red[i * 4 + 1]);
            c = fminf(c, s_red[i * 4 + 2]);
            d = fmaxf(d, s_red[i * 4 + 3]);
        }
        s_bbox[0] = a; s_bbox[1] = b; s_bbox[2] = c; s_bbox[3] = d;
    }
    __syncthreads();

    // ---- Weights: triangle (antialiased bilinear) filter, <=6 taps ----
    // threads [0,64) -> row weights (Wh), threads [64,128) -> col weights (Ww)
    if (tid < OH + OW) {
        bool is_row = (tid < OH);
        int o = is_row ? tid : tid - OH;
        float lo = is_row ? s_bbox[0] : s_bbox[2];
        float hi = is_row ? s_bbox[1] : s_bbox[3];

        float L       = hi - lo + 1.0f;
        float scale   = L * (1.0f / 64.0f);
        float support = fmaxf(scale, 1.0f);
        float center  = scale * ((float)o + 0.5f);
        float base    = lo - 0.5f + center;
        int j0 = (int)ceilf(base - support);
        if (j0 < 0) j0 = 0;
        if (j0 > WW - KT) j0 = WW - KT;

        float wk[KT];
        float s = 0.0f;
        #pragma unroll
        for (int k = 0; k < KT; k++) {
            float j   = (float)(j0 + k);
            float pos = j - lo + 0.5f;
            float t   = (pos - center) / support;
            float wv  = fmaxf(0.0f, 1.0f - fabsf(t));
            if (j < lo || j > hi) wv = 0.0f;
            wk[k] = wv;
            s += wv;
        }
        float invs = 1.0f / fmaxf(s, 1e-12f);
        if (is_row) {
            s_jh[o] = j0;
            #pragma unroll
            for (int k = 0; k < KT; k++) s_wh[o][k] = wk[k] * invs;
        } else {
            s_jw[o] = j0;
            #pragma unroll
            for (int k = 0; k < KT; k++) s_ww[o][k] = wk[k] * invs;
        }
    }
    __syncthreads();

    // ---- Row resize: tmp[o][w] = sum_k Wh[o][k] * img[j0+k][w] ----
    for (int i = tid; i < OH * WW; i += NTHREADS) {
        int o = i >> 7, w = i & 127;
        int j0 = s_jh[o];
        const float* col = simg + j0 * WW + w;
        float acc = 0.0f;
        #pragma unroll
        for (int k = 0; k < KT; k++)
            acc = fmaf(s_wh[o][k], col[k * WW], acc);
        stmp[i] = acc;
    }
    __syncthreads();

    // ---- Col resize + store: out[o][p] = sum_k Ww[p][k] * tmp[o][j0+k] ----
    float* dst = out + (size_t)img * (OH * OW);
    for (int i = tid; i < OH * OW; i += NTHREADS) {
        int o = i >> 6, p = i & 63;
        int j0 = s_jw[p];
        const float* row = stmp + o * WW + j0;
        float acc = 0.0f;
        #pragma unroll
        for (int k = 0; k < KT; k++)
            acc = fmaf(s_ww[p][k], row[k], acc);
        dst[i] = acc;
    }
}

extern "C" void kernel_launch(void* const* d_in, const int* in_sizes, int n_in,
                              void* d_out, int out_size) {
    const float* x = (const float*)d_in[0];
    float* out = (float*)d_out;

    const int smem_bytes = (HH * WW + OH * WW) * (int)sizeof(float);
    cudaFuncSetAttribute(smartpool2d_kernel,
                         cudaFuncAttributeMaxDynamicSharedMemorySize, smem_bytes);

    int nimg = in_sizes[0] / (HH * WW);   // 32 * 128 = 4096
    if (nimg <= 0) return;
    smartpool2d_kernel<<<nimg, NTHREADS, smem_bytes>>>(x, out);
}

// round 4
// speedup vs baseline: 1.1363x; 1.1363x over previous
#include <cuda_runtime.h>
#include <math.h>
#include <float.h>

// SmartPool2d: per-(n,c) 128x128 image -> threshold bbox -> antialiased
// bilinear (triangle) resize of the crop to 64x64.
// One CTA per image, image staged once in smem. Bbox via row/col occupancy
// ballots; resize as 4-tap separable reduction (true triangle support <= 4).

#define HH 128
#define WW 128
#define OH 64
#define OW 64
#define KT 4
#define NT 512
#define NW (NT / 32)

__global__ __launch_bounds__(NT, 2)
void smartpool2d_kernel(const float* __restrict__ x, float* __restrict__ out) {
    extern __shared__ float sm[];
    float* simg = sm;               // 128*128 floats (64 KB)
    float* stmp = sm + HH * WW;     // 64*128 floats (32 KB)
    float4* simg4 = (float4*)simg;
    float4* stmp4 = (float4*)stmp;

    __shared__ float s_wh[KT][OH];
    __shared__ float s_ww[KT][OW];
    __shared__ int   s_jh[OH];
    __shared__ int   s_jw[OW];
    __shared__ float s_red[NW * 2];
    __shared__ unsigned s_cge[32], s_clt[32];
    __shared__ float s_thr;
    __shared__ float s_bbox[4];     // loH, hiH, loW, hiW

    const int tid  = threadIdx.x;
    const int warp = tid >> 5;
    const int lane = tid & 31;
    const float* src = x + (size_t)blockIdx.x * (HH * WW);

    // ---- Pass 1: stage image (float4) + block max ----
    float m = -FLT_MAX;
    {
        const float4* s4 = (const float4*)src;
        #pragma unroll
        for (int it = 0; it < (HH * WW / 4) / NT; it++) {
            int i = tid + it * NT;
            float4 v = s4[i];
            simg4[i] = v;
            m = fmaxf(fmaxf(fmaxf(m, v.x), fmaxf(v.y, v.z)), v.w);
        }
    }
    #pragma unroll
    for (int off = 16; off; off >>= 1)
        m = fmaxf(m, __shfl_xor_sync(0xffffffffu, m, off));
    if (lane == 0) s_red[warp] = m;
    __syncthreads();
    if (tid == 0) {
        float mm = s_red[0];
        #pragma unroll
        for (int i = 1; i < NW; i++) mm = fmaxf(mm, s_red[i]);
        s_thr = 0.1f * mm;
    }
    if (tid >= NT - 32) {  // last warp zeroes column masks (parallel with thr)
        s_cge[tid - (NT - 32)] = 0u;
        s_clt[tid - (NT - 32)] = 0u;
    }
    __syncthreads();
    const float thr = s_thr;

    // ---- Pass 2: bbox via row/col occupancy bits (exact replication) ----
    // Reference values per element: (h==0 ? 1e5 : table*h) for the row axis.
    // Row h>=1 min over w = (any table==0 ? 0 : h); max = (any table==1 ? h : 0).
    // Same per column. Computed with ballots on float4 loads.
    {
        const int rpw = HH / NW;            // rows per warp = 8
        int row0 = warp * rpw;
        unsigned cge = 0u, clt = 0u;
        float wmn = 1e5f, wmx = 0.0f;
        #pragma unroll
        for (int r = 0; r < rpw; r++) {
            int h = row0 + r;
            float4 v = simg4[h * (WW / 4) + lane];
            unsigned g = (unsigned)(v.x >= thr)
                       | ((unsigned)(v.y >= thr) << 1)
                       | ((unsigned)(v.z >= thr) << 2)
                       | ((unsigned)(v.w >= thr) << 3);
            unsigned bge = __ballot_sync(0xffffffffu, g != 0u);
            unsigned blt = __ballot_sync(0xffffffffu, g != 0xFu);
            cge |= g;
            clt |= (~g) & 0xFu;
            if (h > 0) {
                wmn = fminf(wmn, blt ? 0.0f : (float)h);
                wmx = fmaxf(wmx, bge ? (float)h : 0.0f);
            }
        }
        atomicOr(&s_cge[lane], cge);
        atomicOr(&s_clt[lane], clt);
        if (lane == 0) { s_red[warp * 2] = wmn; s_red[warp * 2 + 1] = wmx; }
    }
    __syncthreads();
    if (tid == 0) {
        float xmn = 1e5f, xmx = 0.0f;
        #pragma unroll
        for (int i = 0; i < NW; i++) {
            xmn = fminf(xmn, s_red[i * 2]);
            xmx = fmaxf(xmx, s_red[i * 2 + 1]);
        }
        float ymn = 1e5f, ymx = 0.0f;
        for (int l = 0; l < 32; l++) {
            unsigned g = s_cge[l], t = s_clt[l];
            #pragma unroll
            for (int k = 0; k < 4; k++) {
                int w = 4 * l + k;
                if (w == 0) continue;
                ymn = fminf(ymn, ((t >> k) & 1u) ? 0.0f : (float)w);
                ymx = fmaxf(ymx, ((g >> k) & 1u) ? (float)w : 0.0f);
            }
        }
        s_bbox[0] = xmn; s_bbox[1] = xmx; s_bbox[2] = ymn; s_bbox[3] = ymx;
    }
    __syncthreads();

    // ---- Weights: 4-tap triangle window (support <= 2 => <=4 nonzero taps,
    // all inside [floor(a)+1, floor(a)+4) where a = lo-0.5+center-support) ----
    if (tid < OH + OW) {
        bool isr = tid < OH;
        int o = isr ? tid : tid - OH;
        float lo = isr ? s_bbox[0] : s_bbox[2];
        float hi = isr ? s_bbox[1] : s_bbox[3];

        float L       = hi - lo + 1.0f;
        float scale   = L * (1.0f / 64.0f);
        float support = fmaxf(scale, 1.0f);
        float center  = scale * ((float)o + 0.5f);
        float a       = lo - 0.5f + center - support;
        int j0 = (int)floorf(a) + 1;
        j0 = min(max(j0, 0), WW - KT);

        float wk[KT];
        float s = 0.0f;
        #pragma unroll
        for (int k = 0; k < KT; k++) {
            float j   = (float)(j0 + k);
            float pos = j - lo + 0.5f;
            float t   = (pos - center) / support;
            float wv  = fmaxf(0.0f, 1.0f - fabsf(t));
            if (j < lo || j > hi) wv = 0.0f;
            wk[k] = wv;
            s += wv;
        }
        float sd = fmaxf(s, 1e-12f);
        if (isr) {
            s_jh[o] = j0;
            #pragma unroll
            for (int k = 0; k < KT; k++) s_wh[k][o] = wk[k] / sd;
        } else {
            s_jw[o] = j0;
            #pragma unroll
            for (int k = 0; k < KT; k++) s_ww[k][o] = wk[k] / sd;
        }
    }
    __syncthreads();

    // ---- Row resize (vectorized over w): tmp[o][w] = sum_k Wh[k][o]*img[j0+k][w]
    #pragma unroll
    for (int it = 0; it < (OH * (WW / 4)) / NT; it++) {   // 4 iterations
        int i = tid + it * NT;
        int o = i >> 5, w4 = i & 31;      // warp-uniform o -> broadcast weights
        int j0 = s_jh[o];
        float4 acc = make_float4(0.f, 0.f, 0.f, 0.f);
        #pragma unroll
        for (int k = 0; k < KT; k++) {
            float wv = s_wh[k][o];
            float4 v = simg4[(j0 + k) * (WW / 4) + w4];
            acc.x = fmaf(wv, v.x, acc.x);
            acc.y = fmaf(wv, v.y, acc.y);
            acc.z = fmaf(wv, v.z, acc.z);
            acc.w = fmaf(wv, v.w, acc.w);
        }
        stmp4[o * (WW / 4) + w4] = acc;
    }
    __syncthreads();

    // ---- Col resize + store: out[o][p] = sum_k Ww[k][p]*tmp[o][j0+k] ----
    float* dst = out + (size_t)blockIdx.x * (OH * OW);
    #pragma unroll
    for (int it = 0; it < (OH * OW) / NT; it++) {         // 8 iterations
        int i = tid + it * NT;
        int o = i >> 6, p = i & 63;       // warp-uniform o
        int j0 = s_jw[p];
        const float* row = stmp + o * WW + j0;
        float acc = 0.0f;
        #pragma unroll
        for (int k = 0; k < KT; k++)
            acc = fmaf(s_ww[k][p], row[k], acc);
        dst[i] = acc;
    }
}

extern "C" void kernel_launch(void* const* d_in, const int* in_sizes, int n_in,
                              void* d_out, int out_size) {
    const float* x = (const float*)d_in[0];
    float* out = (float*)d_out;

    const int smem_bytes = (HH * WW + OH * WW) * (int)sizeof(float);
    cudaFuncSetAttribute(smartpool2d_kernel,
                         cudaFuncAttributeMaxDynamicSharedMemorySize, smem_bytes);

    int nimg = in_sizes[0] / (HH * WW);   // 4096
    if (nimg <= 0) return;
    smartpool2d_kernel<<<nimg, NT, smem_bytes>>>(x, out);
}